// round 12
// baseline (speedup 1.0000x reference)
#include <cuda_runtime.h>
#include <cuda_fp16.h>
#include <cstdint>
#include <cstddef>

#define C_IN 256
#define HW 128
#define IMG (HW*HW)
#define NCHUNK 16          // 16 channels (8 k2) per chunk = one k16 MMA step
#define NTAP 5
#define NGROUP 4

#define AS_SZ 2048         // words/stage: 256 pixels x 8 k2 (V); H uses 136x8
#define BROW 136           // words per (t,kq) paired B row (% 32 == 8)
#define BS_SZ (20*BROW)    // 2720 words/stage

// x repacked pixel-major: [img][pix(16384)][c2(128)], word = half2(c even, c odd)
__device__ uint32_t g_xh[(size_t)16*IMG*128];           // 128 MB
// binarized weights, PAIRED: [g][t][q(16)][kq(4)][co(64)][j(2)]
//   j=0 -> k2 = q*8+kq, j=1 -> k2 = q*8+kq+4
__device__ uint32_t g_wb[NGROUP*NTAP*16*4*64*2];

__global__ void prep_weights(const float* __restrict__ w1, const float* __restrict__ w2,
                             const float* __restrict__ w3, const float* __restrict__ w4) {
    int idx = blockIdx.x * blockDim.x + threadIdx.x;     // pair index
    if (idx >= NGROUP*NTAP*16*4*64) return;
    int co = idx & 63;
    int kq = (idx >> 6) & 3;
    int q  = (idx >> 8) & 15;
    int gt = idx >> 12;              // g*5 + t
    int t = gt % 5, g = gt / 5;
    const float* w = g==0?w1:g==1?w2:g==2?w3:w4;
    #pragma unroll
    for (int j = 0; j < 2; j++) {
        int k2 = q*8 + kq + j*4;
        int c0 = 2*k2;
        float v0 = w[((size_t)co*C_IN + c0    )*NTAP + t];
        float v1 = w[((size_t)co*C_IN + c0 + 1)*NTAP + t];
        uint32_t lo = (v0 < 0.f) ? 0xBC00u : 0x3C00u;    // fp16 -1 / +1
        uint32_t hi = (v1 < 0.f) ? 0xBC00u : 0x3C00u;
        g_wb[idx*2 + j] = (hi << 16) | lo;
    }
}

__device__ __forceinline__ uint32_t pack_h2(float a, float b) {
    uint32_t r;
    asm("cvt.rn.f16x2.f32 %0, %1, %2;" : "=r"(r) : "f"(b), "f"(a));
    return r;
}

// Transpose-convert: NCHW fp32 -> [img][pix][c2] half2. Block = 32 pix x 256 ch.
// Writes are uint4 (128B warp-contiguous).
__global__ void convert_x(const float* __restrict__ x) {
    __shared__ float sm[32][257];
    const int bx = blockIdx.x;
    const int img = bx >> 9, pix0 = (bx & 511) * 32;
    const int tid = threadIdx.x;
    const float* xi = x + (size_t)img * C_IN * IMG + pix0;
    #pragma unroll
    for (int it = 0; it < 64; it++) {
        int u = it*128 + tid;
        int c = u >> 5, p = u & 31;
        sm[p][c] = xi[(size_t)c * IMG + p];       // coalesced 128B reads
    }
    __syncthreads();
    uint4* ob4 = reinterpret_cast<uint4*>(g_xh + ((size_t)img * IMG + pix0) * 128);
    #pragma unroll
    for (int it = 0; it < 8; it++) {
        int u = it*128 + tid;                     // [0,1024): 32 pix x 32 uint4
        int p = u >> 5, c4 = u & 31;              // c4 -> channels 8*c4..8*c4+7
        uint4 o;
        o.x = pack_h2(sm[p][8*c4+0], sm[p][8*c4+1]);
        o.y = pack_h2(sm[p][8*c4+2], sm[p][8*c4+3]);
        o.z = pack_h2(sm[p][8*c4+4], sm[p][8*c4+5]);
        o.w = pack_h2(sm[p][8*c4+6], sm[p][8*c4+7]);
        ob4[(size_t)p * 32 + c4] = o;             // coalesced 128B writes
    }
}

#define MMA_F16(cd, A0,A1,A2,A3, B0,B1)                                      \
  asm volatile("mma.sync.aligned.m16n8k16.row.col.f32.f16.f16.f32 "          \
    "{%0,%1,%2,%3},{%4,%5,%6,%7},{%8,%9},{%0,%1,%2,%3};\n"                   \
    : "+f"(cd[0]), "+f"(cd[1]), "+f"(cd[2]), "+f"(cd[3])                     \
    : "r"(A0), "r"(A1), "r"(A2), "r"(A3), "r"(B0), "r"(B1))

#define LDSM4(r0,r1,r2,r3, addr)                                             \
  asm volatile("ldmatrix.sync.aligned.m8n8.x4.shared.b16 {%0,%1,%2,%3}, [%4];" \
    : "=r"(r0), "=r"(r1), "=r"(r2), "=r"(r3) : "r"(addr))

__device__ __forceinline__ void cp_async16(uint32_t dst, const void* src, int src_bytes) {
    asm volatile("cp.async.cg.shared.global [%0], [%1], 16, %2;\n"
                 :: "r"(dst), "l"(src), "r"(src_bytes));
}
__device__ __forceinline__ void cp_commit()  { asm volatile("cp.async.commit_group;\n"); }
__device__ __forceinline__ void cp_wait0()   { asm volatile("cp.async.wait_group 0;\n"); }

// CTA: M=128 pixels x N=64 co. 128 threads = 4 warps (2M x 2N), warp tile 64x32.
// A fragments via ldmatrix.x4 on swizzled pixel-major smem; B via LDS.64 pairs.
// Grid is 1D with GROUP FASTEST: 4 groups of a tile run adjacently -> x shared in L2.
__global__ __launch_bounds__(128, 3) void mrb_conv_kernel(
    const float* __restrict__ bb1, const float* __restrict__ bb2,
    const float* __restrict__ bb3, const float* __restrict__ bb4,
    float* __restrict__ out)
{
    __shared__ uint32_t SA[2][AS_SZ];      // 2 x 8 KB
    __shared__ uint32_t SB[2][BS_SZ];      // 2 x 10.6 KB

    const int g    = blockIdx.x & 3;      // group fastest -> L2 reuse of x records
    const int tile = blockIdx.x >> 2;     // 128 tiles per image
    const bool vert = (g >= 2);
    const bool dil2 = (g & 1);
    const int n = tile >> 7;
    int h0, w0 = 0;
    if (!vert) {
        h0 = tile & 127;                            // 1 row x 128 w
    } else {
        int r = tile & 127;
        h0 = (r >> 3) * 8;  w0 = (r & 7) * 16;      // 8 h x 16 w
    }

    const uint32_t* xb = g_xh + (size_t)n * IMG * 128;   // [pix][c2]

    const int tid  = threadIdx.x;
    const int lane = tid & 31, warp = tid >> 5;
    const int wm = warp >> 1, wn = warp & 1;
    const int qrow = lane >> 2, qcol = lane & 3;

    // ldmatrix lane roles
    const int lrow   = lane & 7;
    const int lm8    = (lane >> 3) & 1;
    const uint32_t khalf16 = (uint32_t)(lane >> 4) << 4;

    float acc[4][4][4];
    #pragma unroll
    for (int i = 0; i < 4; i++)
        #pragma unroll
        for (int j = 0; j < 4; j++)
            #pragma unroll
            for (int r = 0; r < 4; r++) acc[i][j][r] = 0.f;

    // per-mt lane base pixel (row within M tile, before tap shift)
    int pbase[4];
    #pragma unroll
    for (int mt = 0; mt < 4; mt++) {
        int m = wm*64 + mt*16 + lrow + lm8*8;   // 0..127
        pbase[mt] = vert ? (((m >> 4) + 4) * 16 + (m & 15)) : (4 + m);
    }

    const uint32_t saA0 = (uint32_t)__cvta_generic_to_shared(&SA[0][0]);
    const uint32_t saA1 = (uint32_t)__cvta_generic_to_shared(&SA[1][0]);
    const uint32_t sbB0 = (uint32_t)__cvta_generic_to_shared(&SB[0][0]);
    const uint32_t sbB1 = (uint32_t)__cvta_generic_to_shared(&SB[1][0]);

    // issue cp.async copies for chunk q (8 k2 = 16 ch) into stage `buf`
    auto issue = [&](int q, int buf) {
        const uint32_t aB = buf ? saA1 : saA0;
        const uint32_t bB = buf ? sbB1 : sbB0;
        const int k0 = q * 8;             // word offset inside pixel record
        if (!vert) {
            // 136 pixels x 2 chunks = 272 ops
            #pragma unroll
            for (int i = 0; i < 3; i++) {
                int o = tid + i*128;
                if (o < 272) {
                    int pix = o >> 1, h = o & 1;
                    int w = pix - 4;
                    int ok = ((unsigned)w < (unsigned)HW) ? 16 : 0;
                    const uint32_t* src = xb + ((size_t)(h0*HW + (ok ? w : 0)))*128 + k0 + h*4;
                    uint32_t dst = (uint32_t)(pix << 5) + (uint32_t)(h << 4);
                    dst ^= (uint32_t)(pix & 4) << 2;
                    cp_async16(aB + dst, src, ok);
                }
            }
        } else {
            // 256 pixels (16 rows incl halo x 16 w) x 2 chunks = 512 ops
            #pragma unroll
            for (int i = 0; i < 4; i++) {
                int o = tid + i*128;
                int pix = o >> 1, h = o & 1;
                int row = pix >> 4, ww = pix & 15;
                int grow = h0 - 4 + row;
                int ok = ((unsigned)grow < (unsigned)HW) ? 16 : 0;
                const uint32_t* src = xb + ((size_t)((ok ? grow : 0)*HW + w0 + ww))*128 + k0 + h*4;
                uint32_t dst = (uint32_t)(pix << 5) + (uint32_t)(h << 4);
                dst ^= (uint32_t)(pix & 4) << 2;
                cp_async16(aB + dst, src, ok);
            }
        }
        // B paired: 20 rows x 32 x 16B = 640 chunks; 5 per thread
        #pragma unroll
        for (int i = 0; i < 5; i++) {
            int fi = tid + i*128;             // [0,640)
            int c16 = fi & 31, r = fi >> 5;   // r = t*4+kq in [0,20)
            int t = r >> 2, kq = r & 3;
            const uint32_t* srcb =
                g_wb + ((((size_t)(g*NTAP + t)*16 + q)*4 + kq)*64 + c16*2)*2;
            uint32_t dst = bB + (uint32_t)(r*BROW + c16*4) * 4;
            cp_async16(dst, srcb, 16);
        }
        cp_commit();
    };

    issue(0, 0);
    for (int q = 0; q < NCHUNK; q++) {
        cp_wait0();
        __syncthreads();                 // chunk q visible; all warps past chunk q-1 MMAs
        if (q + 1 < NCHUNK) issue(q + 1, (q + 1) & 1);   // overlaps MMAs below

        const uint32_t aStage = (q & 1) ? saA1 : saA0;
        const uint2*   BsP    = reinterpret_cast<const uint2*>(&SB[q & 1][0]);
        #pragma unroll
        for (int t = 0; t < NTAP; t++) {
            int d  = dil2 ? (2*t - 4) : (t - 2);
            int sh = vert ? d * 16 : d;          // tap = pixel shift of A fragment
            uint2 bp[4];
            #pragma unroll
            for (int nt = 0; nt < 4; nt++) {
                int col = wn*32 + nt*8 + qrow;
                bp[nt] = BsP[(t*4 + qcol) * (BROW/2) + col];
            }
            #pragma unroll
            for (int mt = 0; mt < 4; mt++) {
                int p = pbase[mt] + sh;
                uint32_t byte = ((uint32_t)p << 5) + khalf16;
                byte ^= (uint32_t)(p & 4) << 2;
                uint32_t a0, a1, a2, a3;
                LDSM4(a0, a1, a2, a3, aStage + byte);
                #pragma unroll
                for (int nt = 0; nt < 4; nt++)
                    MMA_F16(acc[mt][nt], a0, a1, a2, a3, bp[nt].x, bp[nt].y);
            }
        }
    }

    // Epilogue: bias + store
    const float* bias = (g==0) ? bb1 : (g==1) ? bb2 : (g==2) ? bb3 : bb4;
    float* ob = out + ((size_t)n * 256 + g * 64) * IMG;
    #pragma unroll
    for (int nt = 0; nt < 4; nt++) {
        #pragma unroll
        for (int r = 0; r < 4; r++) {
            int co = wn*32 + nt*8 + 2*qcol + (r & 1);
            float bv = bias[co];
            #pragma unroll
            for (int mt = 0; mt < 4; mt++) {
                int m = wm*64 + mt*16 + qrow + ((r >> 1) << 3);
                int pix = vert ? ((h0 + (m >> 4)) * HW + w0 + (m & 15))
                               : (h0 * HW + m);
                ob[(size_t)co * IMG + pix] = acc[mt][nt][r] + bv;
            }
        }
    }
}

extern "C" void kernel_launch(void* const* d_in, const int* in_sizes, int n_in,
                              void* d_out, int out_size) {
    const float* x  = (const float*)d_in[0];
    const float* w1 = (const float*)d_in[1];
    const float* b1 = (const float*)d_in[2];
    const float* w2 = (const float*)d_in[3];
    const float* b2 = (const float*)d_in[4];
    const float* w3 = (const float*)d_in[5];
    const float* b3 = (const float*)d_in[6];
    const float* w4 = (const float*)d_in[7];
    const float* b4 = (const float*)d_in[8];
    float* out = (float*)d_out;

    prep_weights<<<(NGROUP*NTAP*16*4*64 + 255)/256, 256>>>(w1, w2, w3, w4);
    convert_x<<<16*512, 128>>>(x);
    mrb_conv_kernel<<<16*128*NGROUP, 128>>>(b1, b2, b3, b4, out);
}

// round 13
// speedup vs baseline: 1.0028x; 1.0028x over previous
#include <cuda_runtime.h>
#include <cuda_fp16.h>
#include <cstdint>
#include <cstddef>

#define C_IN 256
#define HW 128
#define IMG (HW*HW)
#define NCHUNK 16          // 16 channels (8 k2) per chunk = one k16 MMA step
#define NTAP 5
#define NGROUP 4

#define AS_SZ 2048         // words/stage: 256 pixels x 8 k2 (V); H uses 136x8
#define BROW 136           // words per (t,kq) paired B row (% 32 == 8)
#define BS_SZ (20*BROW)    // 2720 words/stage

// x repacked pixel-major: [img][pix(16384)][c2(128)], word = half2(c even, c odd)
__device__ uint32_t g_xh[(size_t)16*IMG*128];           // 128 MB
// binarized weights, PAIRED: [g][t][q(16)][kq(4)][co(64)][j(2)]
//   j=0 -> k2 = q*8+kq, j=1 -> k2 = q*8+kq+4
__device__ uint32_t g_wb[NGROUP*NTAP*16*4*64*2];

__global__ void prep_weights(const float* __restrict__ w1, const float* __restrict__ w2,
                             const float* __restrict__ w3, const float* __restrict__ w4) {
    int idx = blockIdx.x * blockDim.x + threadIdx.x;     // pair index
    if (idx >= NGROUP*NTAP*16*4*64) return;
    int co = idx & 63;
    int kq = (idx >> 6) & 3;
    int q  = (idx >> 8) & 15;
    int gt = idx >> 12;              // g*5 + t
    int t = gt % 5, g = gt / 5;
    const float* w = g==0?w1:g==1?w2:g==2?w3:w4;
    #pragma unroll
    for (int j = 0; j < 2; j++) {
        int k2 = q*8 + kq + j*4;
        int c0 = 2*k2;
        float v0 = w[((size_t)co*C_IN + c0    )*NTAP + t];
        float v1 = w[((size_t)co*C_IN + c0 + 1)*NTAP + t];
        uint32_t lo = (v0 < 0.f) ? 0xBC00u : 0x3C00u;    // fp16 -1 / +1
        uint32_t hi = (v1 < 0.f) ? 0xBC00u : 0x3C00u;
        g_wb[idx*2 + j] = (hi << 16) | lo;
    }
}

__device__ __forceinline__ uint32_t pack_h2(float a, float b) {
    uint32_t r;
    asm("cvt.rn.f16x2.f32 %0, %1, %2;" : "=r"(r) : "f"(b), "f"(a));
    return r;
}

// Transpose-convert: NCHW fp32 -> [img][pix][c2] half2. Block = 32 pix x 256 ch.
// Writes are uint4 (128B warp-contiguous).
__global__ void convert_x(const float* __restrict__ x) {
    __shared__ float sm[32][257];
    const int bx = blockIdx.x;
    const int img = bx >> 9, pix0 = (bx & 511) * 32;
    const int tid = threadIdx.x;
    const float* xi = x + (size_t)img * C_IN * IMG + pix0;
    #pragma unroll
    for (int it = 0; it < 64; it++) {
        int u = it*128 + tid;
        int c = u >> 5, p = u & 31;
        sm[p][c] = xi[(size_t)c * IMG + p];       // coalesced 128B reads
    }
    __syncthreads();
    uint4* ob4 = reinterpret_cast<uint4*>(g_xh + ((size_t)img * IMG + pix0) * 128);
    #pragma unroll
    for (int it = 0; it < 8; it++) {
        int u = it*128 + tid;                     // [0,1024): 32 pix x 32 uint4
        int p = u >> 5, c4 = u & 31;              // c4 -> channels 8*c4..8*c4+7
        uint4 o;
        o.x = pack_h2(sm[p][8*c4+0], sm[p][8*c4+1]);
        o.y = pack_h2(sm[p][8*c4+2], sm[p][8*c4+3]);
        o.z = pack_h2(sm[p][8*c4+4], sm[p][8*c4+5]);
        o.w = pack_h2(sm[p][8*c4+6], sm[p][8*c4+7]);
        ob4[(size_t)p * 32 + c4] = o;             // coalesced 128B writes
    }
}

#define MMA_F16(cd, A0,A1,A2,A3, B0,B1)                                      \
  asm volatile("mma.sync.aligned.m16n8k16.row.col.f32.f16.f16.f32 "          \
    "{%0,%1,%2,%3},{%4,%5,%6,%7},{%8,%9},{%0,%1,%2,%3};\n"                   \
    : "+f"(cd[0]), "+f"(cd[1]), "+f"(cd[2]), "+f"(cd[3])                     \
    : "r"(A0), "r"(A1), "r"(A2), "r"(A3), "r"(B0), "r"(B1))

#define LDSM4(r0,r1,r2,r3, addr)                                             \
  asm volatile("ldmatrix.sync.aligned.m8n8.x4.shared.b16 {%0,%1,%2,%3}, [%4];" \
    : "=r"(r0), "=r"(r1), "=r"(r2), "=r"(r3) : "r"(addr))

__device__ __forceinline__ void cp_async16(uint32_t dst, const void* src, int src_bytes) {
    asm volatile("cp.async.cg.shared.global [%0], [%1], 16, %2;\n"
                 :: "r"(dst), "l"(src), "r"(src_bytes));
}
__device__ __forceinline__ void cp_commit()  { asm volatile("cp.async.commit_group;\n"); }
__device__ __forceinline__ void cp_wait0()   { asm volatile("cp.async.wait_group 0;\n"); }

// CTA: M=128 pixels x N=64 co. 128 threads = 4 warps (2M x 2N), warp tile 64x32.
// A fragments via ldmatrix.x4 on swizzled pixel-major smem; B via LDS.64 pairs.
// Grid: blockIdx.y = group (homogeneous concurrent CTAs — R12 showed this matters).
__global__ __launch_bounds__(128, 3) void mrb_conv_kernel(
    const float* __restrict__ bb1, const float* __restrict__ bb2,
    const float* __restrict__ bb3, const float* __restrict__ bb4,
    float* __restrict__ out)
{
    __shared__ uint32_t SA[2][AS_SZ];      // 2 x 8 KB
    __shared__ uint32_t SB[2][BS_SZ];      // 2 x 10.6 KB

    const int g    = blockIdx.y;     // 0:(1,5)d1 1:(1,5)d2 2:(5,1)d1 3:(5,1)d2
    const bool vert = (g >= 2);
    const bool dil2 = (g & 1);
    const int tile = blockIdx.x;     // 128 tiles per image
    const int n = tile >> 7;
    int h0, w0 = 0;
    if (!vert) {
        h0 = tile & 127;                            // 1 row x 128 w
    } else {
        int r = tile & 127;
        h0 = (r >> 3) * 8;  w0 = (r & 7) * 16;      // 8 h x 16 w
    }

    const uint32_t* xb = g_xh + (size_t)n * IMG * 128;   // [pix][c2]

    const int tid  = threadIdx.x;
    const int lane = tid & 31, warp = tid >> 5;
    const int wm = warp >> 1, wn = warp & 1;
    const int qrow = lane >> 2, qcol = lane & 3;

    // ldmatrix lane roles
    const int lrow   = lane & 7;
    const int lm8    = (lane >> 3) & 1;
    const uint32_t khalf16 = (uint32_t)(lane >> 4) << 4;

    float acc[4][4][4];
    #pragma unroll
    for (int i = 0; i < 4; i++)
        #pragma unroll
        for (int j = 0; j < 4; j++)
            #pragma unroll
            for (int r = 0; r < 4; r++) acc[i][j][r] = 0.f;

    // per-mt lane base pixel (row within M tile, before tap shift)
    int pbase[4];
    #pragma unroll
    for (int mt = 0; mt < 4; mt++) {
        int m = wm*64 + mt*16 + lrow + lm8*8;   // 0..127
        pbase[mt] = vert ? (((m >> 4) + 4) * 16 + (m & 15)) : (4 + m);
    }

    const uint32_t saA0 = (uint32_t)__cvta_generic_to_shared(&SA[0][0]);
    const uint32_t saA1 = (uint32_t)__cvta_generic_to_shared(&SA[1][0]);
    const uint32_t sbB0 = (uint32_t)__cvta_generic_to_shared(&SB[0][0]);
    const uint32_t sbB1 = (uint32_t)__cvta_generic_to_shared(&SB[1][0]);

    // issue cp.async copies for chunk q (8 k2 = 16 ch) into stage `buf`
    auto issue = [&](int q, int buf) {
        const uint32_t aB = buf ? saA1 : saA0;
        const uint32_t bB = buf ? sbB1 : sbB0;
        const int k0 = q * 8;             // word offset inside pixel record
        if (!vert) {
            // 136 pixels x 2 chunks = 272 ops
            #pragma unroll
            for (int i = 0; i < 3; i++) {
                int o = tid + i*128;
                if (o < 272) {
                    int pix = o >> 1, h = o & 1;
                    int w = pix - 4;
                    int ok = ((unsigned)w < (unsigned)HW) ? 16 : 0;
                    const uint32_t* src = xb + ((size_t)(h0*HW + (ok ? w : 0)))*128 + k0 + h*4;
                    uint32_t dst = (uint32_t)(pix << 5) + (uint32_t)(h << 4);
                    dst ^= (uint32_t)(pix & 4) << 2;
                    cp_async16(aB + dst, src, ok);
                }
            }
        } else {
            // 256 pixels (16 rows incl halo x 16 w) x 2 chunks = 512 ops
            #pragma unroll
            for (int i = 0; i < 4; i++) {
                int o = tid + i*128;
                int pix = o >> 1, h = o & 1;
                int row = pix >> 4, ww = pix & 15;
                int grow = h0 - 4 + row;
                int ok = ((unsigned)grow < (unsigned)HW) ? 16 : 0;
                const uint32_t* src = xb + ((size_t)((ok ? grow : 0)*HW + w0 + ww))*128 + k0 + h*4;
                uint32_t dst = (uint32_t)(pix << 5) + (uint32_t)(h << 4);
                dst ^= (uint32_t)(pix & 4) << 2;
                cp_async16(aB + dst, src, ok);
            }
        }
        // B paired: 20 rows x 32 x 16B = 640 chunks; 5 per thread
        #pragma unroll
        for (int i = 0; i < 5; i++) {
            int fi = tid + i*128;             // [0,640)
            int c16 = fi & 31, r = fi >> 5;   // r = t*4+kq in [0,20)
            int t = r >> 2, kq = r & 3;
            const uint32_t* srcb =
                g_wb + ((((size_t)(g*NTAP + t)*16 + q)*4 + kq)*64 + c16*2)*2;
            uint32_t dst = bB + (uint32_t)(r*BROW + c16*4) * 4;
            cp_async16(dst, srcb, 16);
        }
        cp_commit();
    };

    issue(0, 0);
    for (int q = 0; q < NCHUNK; q++) {
        cp_wait0();
        __syncthreads();                 // chunk q visible; all warps past chunk q-1 MMAs
        if (q + 1 < NCHUNK) issue(q + 1, (q + 1) & 1);   // overlaps MMAs below

        const uint32_t aStage = (q & 1) ? saA1 : saA0;
        const uint2*   BsP    = reinterpret_cast<const uint2*>(&SB[q & 1][0]);
        #pragma unroll
        for (int t = 0; t < NTAP; t++) {
            int d  = dil2 ? (2*t - 4) : (t - 2);
            int sh = vert ? d * 16 : d;          // tap = pixel shift of A fragment
            uint2 bp[4];
            #pragma unroll
            for (int nt = 0; nt < 4; nt++) {
                int col = wn*32 + nt*8 + qrow;
                bp[nt] = BsP[(t*4 + qcol) * (BROW/2) + col];
            }
            #pragma unroll
            for (int mt = 0; mt < 4; mt++) {
                int p = pbase[mt] + sh;
                uint32_t byte = ((uint32_t)p << 5) + khalf16;
                byte ^= (uint32_t)(p & 4) << 2;
                uint32_t a0, a1, a2, a3;
                LDSM4(a0, a1, a2, a3, aStage + byte);
                #pragma unroll
                for (int nt = 0; nt < 4; nt++)
                    MMA_F16(acc[mt][nt], a0, a1, a2, a3, bp[nt].x, bp[nt].y);
            }
        }
    }

    // Epilogue: bias + store
    const float* bias = (g==0) ? bb1 : (g==1) ? bb2 : (g==2) ? bb3 : bb4;
    float* ob = out + ((size_t)n * 256 + g * 64) * IMG;
    #pragma unroll
    for (int nt = 0; nt < 4; nt++) {
        #pragma unroll
        for (int r = 0; r < 4; r++) {
            int co = wn*32 + nt*8 + 2*qcol + (r & 1);
            float bv = bias[co];
            #pragma unroll
            for (int mt = 0; mt < 4; mt++) {
                int m = wm*64 + mt*16 + qrow + ((r >> 1) << 3);
                int pix = vert ? ((h0 + (m >> 4)) * HW + w0 + (m & 15))
                               : (h0 * HW + m);
                ob[(size_t)co * IMG + pix] = acc[mt][nt][r] + bv;
            }
        }
    }
}

extern "C" void kernel_launch(void* const* d_in, const int* in_sizes, int n_in,
                              void* d_out, int out_size) {
    const float* x  = (const float*)d_in[0];
    const float* w1 = (const float*)d_in[1];
    const float* b1 = (const float*)d_in[2];
    const float* w2 = (const float*)d_in[3];
    const float* b2 = (const float*)d_in[4];
    const float* w3 = (const float*)d_in[5];
    const float* b3 = (const float*)d_in[6];
    const float* w4 = (const float*)d_in[7];
    const float* b4 = (const float*)d_in[8];
    float* out = (float*)d_out;

    prep_weights<<<(NGROUP*NTAP*16*4*64 + 255)/256, 256>>>(w1, w2, w3, w4);
    convert_x<<<16*512, 128>>>(x);
    dim3 grid(16 * 128, NGROUP);
    mrb_conv_kernel<<<grid, 128>>>(b1, b2, b3, b4, out);
}

// round 14
// speedup vs baseline: 1.2484x; 1.2450x over previous
#include <cuda_runtime.h>
#include <cuda_fp16.h>
#include <cstdint>
#include <cstddef>

#define C_IN 256
#define HW 128
#define IMG (HW*HW)
#define NCHUNK 16          // 16 channels (8 k2) per chunk = one k16 MMA step
#define NSTAGE 3
#define NTAP 5
#define NGROUP 4

#define AS_SZ 2048         // words/stage: 256 pixels x 8 k2 (V); H uses 136x8
#define BROW 136           // words per (t,kq) paired B row (% 32 == 8)
#define BS_SZ (20*BROW)    // 2720 words/stage
#define SMEM_BYTES (NSTAGE*(AS_SZ+BS_SZ)*4)   // 57216

// x repacked pixel-major: [img][pix(16384)][c2(128)], word = half2(c even, c odd)
__device__ uint32_t g_xh[(size_t)16*IMG*128];           // 128 MB
// binarized weights, PAIRED: [g][t][q(16)][kq(4)][co(64)][j(2)]
//   j=0 -> k2 = q*8+kq, j=1 -> k2 = q*8+kq+4
__device__ uint32_t g_wb[NGROUP*NTAP*16*4*64*2];

__global__ void prep_weights(const float* __restrict__ w1, const float* __restrict__ w2,
                             const float* __restrict__ w3, const float* __restrict__ w4) {
    int idx = blockIdx.x * blockDim.x + threadIdx.x;     // pair index
    if (idx >= NGROUP*NTAP*16*4*64) return;
    int co = idx & 63;
    int kq = (idx >> 6) & 3;
    int q  = (idx >> 8) & 15;
    int gt = idx >> 12;              // g*5 + t
    int t = gt % 5, g = gt / 5;
    const float* w = g==0?w1:g==1?w2:g==2?w3:w4;
    #pragma unroll
    for (int j = 0; j < 2; j++) {
        int k2 = q*8 + kq + j*4;
        int c0 = 2*k2;
        float v0 = w[((size_t)co*C_IN + c0    )*NTAP + t];
        float v1 = w[((size_t)co*C_IN + c0 + 1)*NTAP + t];
        uint32_t lo = (v0 < 0.f) ? 0xBC00u : 0x3C00u;    // fp16 -1 / +1
        uint32_t hi = (v1 < 0.f) ? 0xBC00u : 0x3C00u;
        g_wb[idx*2 + j] = (hi << 16) | lo;
    }
}

__device__ __forceinline__ uint32_t pack_h2(float a, float b) {
    uint32_t r;
    asm("cvt.rn.f16x2.f32 %0, %1, %2;" : "=r"(r) : "f"(b), "f"(a));
    return r;
}

// Transpose-convert: NCHW fp32 -> [img][pix][c2] half2. Block = 32 pix x 256 ch.
// R11 version: scalar stores (already coalesced: 128 consecutive words/iter).
__global__ void convert_x(const float* __restrict__ x) {
    __shared__ float sm[32][257];
    const int bx = blockIdx.x;
    const int img = bx >> 9, pix0 = (bx & 511) * 32;
    const int tid = threadIdx.x;
    const float* xi = x + (size_t)img * C_IN * IMG + pix0;
    #pragma unroll
    for (int it = 0; it < 64; it++) {
        int u = it*128 + tid;
        int c = u >> 5, p = u & 31;
        sm[p][c] = xi[(size_t)c * IMG + p];       // coalesced 128B reads
    }
    __syncthreads();
    uint32_t* ob = g_xh + ((size_t)img * IMG + pix0) * 128;
    #pragma unroll
    for (int it = 0; it < 32; it++) {
        int p = it, c2 = tid;                     // 128 threads = 128 c2
        ob[(size_t)p * 128 + c2] = pack_h2(sm[p][2*c2], sm[p][2*c2+1]);
    }
}

#define MMA_F16(cd, A0,A1,A2,A3, B0,B1)                                      \
  asm volatile("mma.sync.aligned.m16n8k16.row.col.f32.f16.f16.f32 "          \
    "{%0,%1,%2,%3},{%4,%5,%6,%7},{%8,%9},{%0,%1,%2,%3};\n"                   \
    : "+f"(cd[0]), "+f"(cd[1]), "+f"(cd[2]), "+f"(cd[3])                     \
    : "r"(A0), "r"(A1), "r"(A2), "r"(A3), "r"(B0), "r"(B1))

#define LDSM4(r0,r1,r2,r3, addr)                                             \
  asm volatile("ldmatrix.sync.aligned.m8n8.x4.shared.b16 {%0,%1,%2,%3}, [%4];" \
    : "=r"(r0), "=r"(r1), "=r"(r2), "=r"(r3) : "r"(addr))

__device__ __forceinline__ void cp_async16(uint32_t dst, const void* src, int src_bytes) {
    asm volatile("cp.async.cg.shared.global [%0], [%1], 16, %2;\n"
                 :: "r"(dst), "l"(src), "r"(src_bytes));
}
__device__ __forceinline__ void cp_commit()  { asm volatile("cp.async.commit_group;\n"); }
__device__ __forceinline__ void cp_wait0()   { asm volatile("cp.async.wait_group 0;\n"); }
__device__ __forceinline__ void cp_wait1()   { asm volatile("cp.async.wait_group 1;\n"); }

// CTA: M=128 pixels x N=64 co. 128 threads = 4 warps (2M x 2N), warp tile 64x32.
// A fragments via ldmatrix.x4 on swizzled pixel-major smem; B via LDS.64 pairs.
// 3-stage cp.async ring (dynamic smem): copies land 2 compute phases early.
__global__ __launch_bounds__(128, 3) void mrb_conv_kernel(
    const float* __restrict__ bb1, const float* __restrict__ bb2,
    const float* __restrict__ bb3, const float* __restrict__ bb4,
    float* __restrict__ out)
{
    extern __shared__ uint32_t dynsm[];    // [3 x AS_SZ][3 x BS_SZ]

    const int g    = blockIdx.y;     // 0:(1,5)d1 1:(1,5)d2 2:(5,1)d1 3:(5,1)d2
    const bool vert = (g >= 2);
    const bool dil2 = (g & 1);
    const int tile = blockIdx.x;     // 128 tiles per image
    const int n = tile >> 7;
    int h0, w0 = 0;
    if (!vert) {
        h0 = tile & 127;                            // 1 row x 128 w
    } else {
        int r = tile & 127;
        h0 = (r >> 3) * 8;  w0 = (r & 7) * 16;      // 8 h x 16 w
    }

    const uint32_t* xb = g_xh + (size_t)n * IMG * 128;   // [pix][c2]

    const int tid  = threadIdx.x;
    const int lane = tid & 31, warp = tid >> 5;
    const int wm = warp >> 1, wn = warp & 1;
    const int qrow = lane >> 2, qcol = lane & 3;

    // ldmatrix lane roles
    const int lrow   = lane & 7;
    const int lm8    = (lane >> 3) & 1;
    const uint32_t khalf16 = (uint32_t)(lane >> 4) << 4;

    float acc[4][4][4];
    #pragma unroll
    for (int i = 0; i < 4; i++)
        #pragma unroll
        for (int j = 0; j < 4; j++)
            #pragma unroll
            for (int r = 0; r < 4; r++) acc[i][j][r] = 0.f;

    // per-mt lane base pixel (row within M tile, before tap shift)
    int pbase[4];
    #pragma unroll
    for (int mt = 0; mt < 4; mt++) {
        int m = wm*64 + mt*16 + lrow + lm8*8;   // 0..127
        pbase[mt] = vert ? (((m >> 4) + 4) * 16 + (m & 15)) : (4 + m);
    }

    const uint32_t smBase = (uint32_t)__cvta_generic_to_shared(dynsm);

    // issue cp.async copies for chunk q (8 k2 = 16 ch) into stage `buf`
    auto issue = [&](int q, int buf) {
        const uint32_t aB = smBase + (uint32_t)(buf * AS_SZ) * 4;
        const uint32_t bB = smBase + (uint32_t)(NSTAGE*AS_SZ + buf * BS_SZ) * 4;
        const int k0 = q * 8;             // word offset inside pixel record
        if (!vert) {
            // 136 pixels x 2 chunks = 272 ops
            #pragma unroll
            for (int i = 0; i < 3; i++) {
                int o = tid + i*128;
                if (o < 272) {
                    int pix = o >> 1, h = o & 1;
                    int w = pix - 4;
                    int ok = ((unsigned)w < (unsigned)HW) ? 16 : 0;
                    const uint32_t* src = xb + ((size_t)(h0*HW + (ok ? w : 0)))*128 + k0 + h*4;
                    uint32_t dst = (uint32_t)(pix << 5) + (uint32_t)(h << 4);
                    dst ^= (uint32_t)(pix & 4) << 2;
                    cp_async16(aB + dst, src, ok);
                }
            }
        } else {
            // 256 pixels (16 rows incl halo x 16 w) x 2 chunks = 512 ops
            #pragma unroll
            for (int i = 0; i < 4; i++) {
                int o = tid + i*128;
                int pix = o >> 1, h = o & 1;
                int row = pix >> 4, ww = pix & 15;
                int grow = h0 - 4 + row;
                int ok = ((unsigned)grow < (unsigned)HW) ? 16 : 0;
                const uint32_t* src = xb + ((size_t)((ok ? grow : 0)*HW + w0 + ww))*128 + k0 + h*4;
                uint32_t dst = (uint32_t)(pix << 5) + (uint32_t)(h << 4);
                dst ^= (uint32_t)(pix & 4) << 2;
                cp_async16(aB + dst, src, ok);
            }
        }
        // B paired: 20 rows x 32 x 16B = 640 chunks; 5 per thread
        #pragma unroll
        for (int i = 0; i < 5; i++) {
            int fi = tid + i*128;             // [0,640)
            int c16 = fi & 31, r = fi >> 5;   // r = t*4+kq in [0,20)
            int t = r >> 2, kq = r & 3;
            const uint32_t* srcb =
                g_wb + ((((size_t)(g*NTAP + t)*16 + q)*4 + kq)*64 + c16*2)*2;
            uint32_t dst = bB + (uint32_t)(r*BROW + c16*4) * 4;
            cp_async16(dst, srcb, 16);
        }
        cp_commit();
    };

    issue(0, 0);
    issue(1, 1);
    int buf = 0;
    for (int q = 0; q < NCHUNK; q++) {
        if (q + 1 < NCHUNK) cp_wait1();   // chunk q landed; q+1 may still fly
        else                cp_wait0();
        __syncthreads();                  // all warps past compute(q-1); stage reusable
        if (q + 2 < NCHUNK) {
            int nb = buf + 2; if (nb >= NSTAGE) nb -= NSTAGE;
            issue(q + 2, nb);             // lands ~2 compute phases ahead of its wait
        }

        const uint32_t aStage = smBase + (uint32_t)(buf * AS_SZ) * 4;
        const uint2*   BsP    = reinterpret_cast<const uint2*>(
                                  dynsm + NSTAGE*AS_SZ + buf * BS_SZ);
        #pragma unroll
        for (int t = 0; t < NTAP; t++) {
            int d  = dil2 ? (2*t - 4) : (t - 2);
            int sh = vert ? d * 16 : d;          // tap = pixel shift of A fragment
            uint2 bp[4];
            #pragma unroll
            for (int nt = 0; nt < 4; nt++) {
                int col = wn*32 + nt*8 + qrow;
                bp[nt] = BsP[(t*4 + qcol) * (BROW/2) + col];
            }
            #pragma unroll
            for (int mt = 0; mt < 4; mt++) {
                int p = pbase[mt] + sh;
                uint32_t byte = ((uint32_t)p << 5) + khalf16;
                byte ^= (uint32_t)(p & 4) << 2;
                uint32_t a0, a1, a2, a3;
                LDSM4(a0, a1, a2, a3, aStage + byte);
                #pragma unroll
                for (int nt = 0; nt < 4; nt++)
                    MMA_F16(acc[mt][nt], a0, a1, a2, a3, bp[nt].x, bp[nt].y);
            }
        }
        if (++buf >= NSTAGE) buf = 0;
    }

    // Epilogue: bias + store
    const float* bias = (g==0) ? bb1 : (g==1) ? bb2 : (g==2) ? bb3 : bb4;
    float* ob = out + ((size_t)n * 256 + g * 64) * IMG;
    #pragma unroll
    for (int nt = 0; nt < 4; nt++) {
        #pragma unroll
        for (int r = 0; r < 4; r++) {
            int co = wn*32 + nt*8 + 2*qcol + (r & 1);
            float bv = bias[co];
            #pragma unroll
            for (int mt = 0; mt < 4; mt++) {
                int m = wm*64 + mt*16 + qrow + ((r >> 1) << 3);
                int pix = vert ? ((h0 + (m >> 4)) * HW + w0 + (m & 15))
                               : (h0 * HW + m);
                ob[(size_t)co * IMG + pix] = acc[mt][nt][r] + bv;
            }
        }
    }
}

extern "C" void kernel_launch(void* const* d_in, const int* in_sizes, int n_in,
                              void* d_out, int out_size) {
    const float* x  = (const float*)d_in[0];
    const float* w1 = (const float*)d_in[1];
    const float* b1 = (const float*)d_in[2];
    const float* w2 = (const float*)d_in[3];
    const float* b2 = (const float*)d_in[4];
    const float* w3 = (const float*)d_in[5];
    const float* b3 = (const float*)d_in[6];
    const float* w4 = (const float*)d_in[7];
    const float* b4 = (const float*)d_in[8];
    float* out = (float*)d_out;

    cudaFuncSetAttribute(mrb_conv_kernel,
                         cudaFuncAttributeMaxDynamicSharedMemorySize, SMEM_BYTES);

    prep_weights<<<(NGROUP*NTAP*16*4*64 + 255)/256, 256>>>(w1, w2, w3, w4);
    convert_x<<<16*512, 128>>>(x);
    dim3 grid(16 * 128, NGROUP);
    mrb_conv_kernel<<<grid, 128, SMEM_BYTES>>>(b1, b2, b3, b4, out);
}

// round 15
// speedup vs baseline: 1.2599x; 1.0092x over previous
#include <cuda_runtime.h>
#include <cuda_fp16.h>
#include <cstdint>
#include <cstddef>

#define C_IN 256
#define HW 128
#define IMG (HW*HW)
#define NCHUNK 16          // 16 channels (8 k2) per chunk = one k16 MMA step
#define NTAP 5
#define NGROUP 4

#define AS_SZ 2048         // words/stage: 256 pixels x 8 k2 (V); H uses 136x8
#define BROW 136           // words per (t,kq) paired B row (% 32 == 8)
#define BS_SZ (20*BROW)    // 2720 words/stage

// x repacked pixel-major: [img][pix(16384)][c2(128)], word = half2(c even, c odd)
__device__ uint32_t g_xh[(size_t)16*IMG*128];           // 128 MB
// binarized weights, PAIRED: [g][t][q(16)][kq(4)][co(64)][j(2)]
//   j=0 -> k2 = q*8+kq, j=1 -> k2 = q*8+kq+4
__device__ uint32_t g_wb[NGROUP*NTAP*16*4*64*2];

__global__ void prep_weights(const float* __restrict__ w1, const float* __restrict__ w2,
                             const float* __restrict__ w3, const float* __restrict__ w4) {
    int idx = blockIdx.x * blockDim.x + threadIdx.x;     // pair index
    if (idx >= NGROUP*NTAP*16*4*64) return;
    int co = idx & 63;
    int kq = (idx >> 6) & 3;
    int q  = (idx >> 8) & 15;
    int gt = idx >> 12;              // g*5 + t
    int t = gt % 5, g = gt / 5;
    const float* w = g==0?w1:g==1?w2:g==2?w3:w4;
    #pragma unroll
    for (int j = 0; j < 2; j++) {
        int k2 = q*8 + kq + j*4;
        int c0 = 2*k2;
        float v0 = w[((size_t)co*C_IN + c0    )*NTAP + t];
        float v1 = w[((size_t)co*C_IN + c0 + 1)*NTAP + t];
        uint32_t lo = (v0 < 0.f) ? 0xBC00u : 0x3C00u;    // fp16 -1 / +1
        uint32_t hi = (v1 < 0.f) ? 0xBC00u : 0x3C00u;
        g_wb[idx*2 + j] = (hi << 16) | lo;
    }
}

__device__ __forceinline__ uint32_t pack_h2(float a, float b) {
    uint32_t r;
    asm("cvt.rn.f16x2.f32 %0, %1, %2;" : "=r"(r) : "f"(b), "f"(a));
    return r;
}

// Transpose-convert: NCHW fp32 -> [img][pix][c2] half2. Block = 32 pix x 256 ch.
// R11 version: scalar stores (already coalesced: 128 consecutive words/iter).
__global__ void convert_x(const float* __restrict__ x) {
    __shared__ float sm[32][257];
    const int bx = blockIdx.x;
    const int img = bx >> 9, pix0 = (bx & 511) * 32;
    const int tid = threadIdx.x;
    const float* xi = x + (size_t)img * C_IN * IMG + pix0;
    #pragma unroll
    for (int it = 0; it < 64; it++) {
        int u = it*128 + tid;
        int c = u >> 5, p = u & 31;
        sm[p][c] = xi[(size_t)c * IMG + p];       // coalesced 128B reads
    }
    __syncthreads();
    uint32_t* ob = g_xh + ((size_t)img * IMG + pix0) * 128;
    #pragma unroll
    for (int it = 0; it < 32; it++) {
        int p = it, c2 = tid;                     // 128 threads = 128 c2
        ob[(size_t)p * 128 + c2] = pack_h2(sm[p][2*c2], sm[p][2*c2+1]);
    }
}

#define MMA_F16(cd, A0,A1,A2,A3, B0,B1)                                      \
  asm volatile("mma.sync.aligned.m16n8k16.row.col.f32.f16.f16.f32 "          \
    "{%0,%1,%2,%3},{%4,%5,%6,%7},{%8,%9},{%0,%1,%2,%3};\n"                   \
    : "+f"(cd[0]), "+f"(cd[1]), "+f"(cd[2]), "+f"(cd[3])                     \
    : "r"(A0), "r"(A1), "r"(A2), "r"(A3), "r"(B0), "r"(B1))

#define LDSM4(r0,r1,r2,r3, addr)                                             \
  asm volatile("ldmatrix.sync.aligned.m8n8.x4.shared.b16 {%0,%1,%2,%3}, [%4];" \
    : "=r"(r0), "=r"(r1), "=r"(r2), "=r"(r3) : "r"(addr))

__device__ __forceinline__ void cp_async16(uint32_t dst, const void* src, int src_bytes) {
    asm volatile("cp.async.cg.shared.global [%0], [%1], 16, %2;\n"
                 :: "r"(dst), "l"(src), "r"(src_bytes));
}
__device__ __forceinline__ void cp_commit()  { asm volatile("cp.async.commit_group;\n"); }
__device__ __forceinline__ void cp_wait0()   { asm volatile("cp.async.wait_group 0;\n"); }

// CTA: M=128 pixels x N=64 co. 128 threads = 4 warps (2M x 2N), warp tile 64x32.
// A fragments via ldmatrix.x4 on swizzled pixel-major smem; B via LDS.64 pairs.
// 2-stage ring, static smem (38.1 KB), reg-capped for 4 CTAs = 16 warps/SM.
__global__ __launch_bounds__(128, 4) void mrb_conv_kernel(
    const float* __restrict__ bb1, const float* __restrict__ bb2,
    const float* __restrict__ bb3, const float* __restrict__ bb4,
    float* __restrict__ out)
{
    __shared__ uint32_t SA[2][AS_SZ];      // 2 x 8 KB
    __shared__ uint32_t SB[2][BS_SZ];      // 2 x 10.6 KB

    const int g    = blockIdx.y;     // 0:(1,5)d1 1:(1,5)d2 2:(5,1)d1 3:(5,1)d2
    const bool vert = (g >= 2);
    const bool dil2 = (g & 1);
    const int tile = blockIdx.x;     // 128 tiles per image
    const int n = tile >> 7;
    int h0, w0 = 0;
    if (!vert) {
        h0 = tile & 127;                            // 1 row x 128 w
    } else {
        int r = tile & 127;
        h0 = (r >> 3) * 8;  w0 = (r & 7) * 16;      // 8 h x 16 w
    }

    const uint32_t* xb = g_xh + (size_t)n * IMG * 128;   // [pix][c2]

    const int tid  = threadIdx.x;
    const int lane = tid & 31, warp = tid >> 5;
    const int wm = warp >> 1, wn = warp & 1;
    const int qrow = lane >> 2, qcol = lane & 3;

    // ldmatrix lane roles
    const int lrow   = lane & 7;
    const int lm8    = (lane >> 3) & 1;
    const uint32_t khalf16 = (uint32_t)(lane >> 4) << 4;

    float acc[4][4][4];
    #pragma unroll
    for (int i = 0; i < 4; i++)
        #pragma unroll
        for (int j = 0; j < 4; j++)
            #pragma unroll
            for (int r = 0; r < 4; r++) acc[i][j][r] = 0.f;

    // per-mt lane base pixel (row within M tile, before tap shift)
    int pbase[4];
    #pragma unroll
    for (int mt = 0; mt < 4; mt++) {
        int m = wm*64 + mt*16 + lrow + lm8*8;   // 0..127
        pbase[mt] = vert ? (((m >> 4) + 4) * 16 + (m & 15)) : (4 + m);
    }

    const uint32_t saA0 = (uint32_t)__cvta_generic_to_shared(&SA[0][0]);
    const uint32_t saA1 = (uint32_t)__cvta_generic_to_shared(&SA[1][0]);
    const uint32_t sbB0 = (uint32_t)__cvta_generic_to_shared(&SB[0][0]);
    const uint32_t sbB1 = (uint32_t)__cvta_generic_to_shared(&SB[1][0]);

    // issue cp.async copies for chunk q (8 k2 = 16 ch) into stage `buf`
    auto issue = [&](int q, int buf) {
        const uint32_t aB = buf ? saA1 : saA0;
        const uint32_t bB = buf ? sbB1 : sbB0;
        const int k0 = q * 8;             // word offset inside pixel record
        if (!vert) {
            // 136 pixels x 2 chunks = 272 ops
            #pragma unroll
            for (int i = 0; i < 3; i++) {
                int o = tid + i*128;
                if (o < 272) {
                    int pix = o >> 1, h = o & 1;
                    int w = pix - 4;
                    int ok = ((unsigned)w < (unsigned)HW) ? 16 : 0;
                    const uint32_t* src = xb + ((size_t)(h0*HW + (ok ? w : 0)))*128 + k0 + h*4;
                    uint32_t dst = (uint32_t)(pix << 5) + (uint32_t)(h << 4);
                    dst ^= (uint32_t)(pix & 4) << 2;
                    cp_async16(aB + dst, src, ok);
                }
            }
        } else {
            // 256 pixels (16 rows incl halo x 16 w) x 2 chunks = 512 ops
            #pragma unroll
            for (int i = 0; i < 4; i++) {
                int o = tid + i*128;
                int pix = o >> 1, h = o & 1;
                int row = pix >> 4, ww = pix & 15;
                int grow = h0 - 4 + row;
                int ok = ((unsigned)grow < (unsigned)HW) ? 16 : 0;
                const uint32_t* src = xb + ((size_t)((ok ? grow : 0)*HW + w0 + ww))*128 + k0 + h*4;
                uint32_t dst = (uint32_t)(pix << 5) + (uint32_t)(h << 4);
                dst ^= (uint32_t)(pix & 4) << 2;
                cp_async16(aB + dst, src, ok);
            }
        }
        // B paired: 20 rows x 32 x 16B = 640 chunks; 5 per thread
        #pragma unroll
        for (int i = 0; i < 5; i++) {
            int fi = tid + i*128;             // [0,640)
            int c16 = fi & 31, r = fi >> 5;   // r = t*4+kq in [0,20)
            int t = r >> 2, kq = r & 3;
            const uint32_t* srcb =
                g_wb + ((((size_t)(g*NTAP + t)*16 + q)*4 + kq)*64 + c16*2)*2;
            uint32_t dst = bB + (uint32_t)(r*BROW + c16*4) * 4;
            cp_async16(dst, srcb, 16);
        }
        cp_commit();
    };

    issue(0, 0);
    for (int q = 0; q < NCHUNK; q++) {
        cp_wait0();
        __syncthreads();                 // chunk q visible; all warps past chunk q-1 MMAs
        if (q + 1 < NCHUNK) issue(q + 1, (q + 1) & 1);   // overlaps MMAs below

        const uint32_t aStage = (q & 1) ? saA1 : saA0;
        const uint2*   BsP    = reinterpret_cast<const uint2*>(&SB[q & 1][0]);
        #pragma unroll
        for (int t = 0; t < NTAP; t++) {
            int d  = dil2 ? (2*t - 4) : (t - 2);
            int sh = vert ? d * 16 : d;          // tap = pixel shift of A fragment
            uint2 bp[4];
            #pragma unroll
            for (int nt = 0; nt < 4; nt++) {
                int col = wn*32 + nt*8 + qrow;
                bp[nt] = BsP[(t*4 + qcol) * (BROW/2) + col];
            }
            #pragma unroll
            for (int mt = 0; mt < 4; mt++) {
                int p = pbase[mt] + sh;
                uint32_t byte = ((uint32_t)p << 5) + khalf16;
                byte ^= (uint32_t)(p & 4) << 2;
                uint32_t a0, a1, a2, a3;
                LDSM4(a0, a1, a2, a3, aStage + byte);
                #pragma unroll
                for (int nt = 0; nt < 4; nt++)
                    MMA_F16(acc[mt][nt], a0, a1, a2, a3, bp[nt].x, bp[nt].y);
            }
        }
    }

    // Epilogue: bias + store
    const float* bias = (g==0) ? bb1 : (g==1) ? bb2 : (g==2) ? bb3 : bb4;
    float* ob = out + ((size_t)n * 256 + g * 64) * IMG;
    #pragma unroll
    for (int nt = 0; nt < 4; nt++) {
        #pragma unroll
        for (int r = 0; r < 4; r++) {
            int co = wn*32 + nt*8 + 2*qcol + (r & 1);
            float bv = bias[co];
            #pragma unroll
            for (int mt = 0; mt < 4; mt++) {
                int m = wm*64 + mt*16 + qrow + ((r >> 1) << 3);
                int pix = vert ? ((h0 + (m >> 4)) * HW + w0 + (m & 15))
                               : (h0 * HW + m);
                ob[(size_t)co * IMG + pix] = acc[mt][nt][r] + bv;
            }
        }
    }
}

extern "C" void kernel_launch(void* const* d_in, const int* in_sizes, int n_in,
                              void* d_out, int out_size) {
    const float* x  = (const float*)d_in[0];
    const float* w1 = (const float*)d_in[1];
    const float* b1 = (const float*)d_in[2];
    const float* w2 = (const float*)d_in[3];
    const float* b2 = (const float*)d_in[4];
    const float* w3 = (const float*)d_in[5];
    const float* b3 = (const float*)d_in[6];
    const float* w4 = (const float*)d_in[7];
    const float* b4 = (const float*)d_in[8];
    float* out = (float*)d_out;

    prep_weights<<<(NGROUP*NTAP*16*4*64 + 255)/256, 256>>>(w1, w2, w3, w4);
    convert_x<<<16*512, 128>>>(x);
    dim3 grid(16 * 128, NGROUP);
    mrb_conv_kernel<<<grid, 128>>>(b1, b2, b3, b4, out);
}

// round 16
// speedup vs baseline: 1.2602x; 1.0002x over previous
#include <cuda_runtime.h>
#include <cuda_fp16.h>
#include <cstdint>
#include <cstddef>

#define C_IN 256
#define HW 128
#define IMG (HW*HW)
#define NCHUNK 16          // 16 channels (8 k2) per chunk = one k16 MMA step
#define NTAP 5
#define NGROUP 4

#define AS_SZ 2048         // words/stage: 256 pixels x 8 k2 (V); H uses 136x8
#define BROW 136           // words per (t,kq) paired B row (% 32 == 8)
#define BS_SZ (20*BROW)    // 2720 words/stage

// x repacked pixel-major: [img][pix(16384)][c2(128)], word = half2(c even, c odd)
__device__ uint32_t g_xh[(size_t)16*IMG*128];           // 128 MB
// binarized weights, PAIRED: [g][t][q(16)][kq(4)][co(64)][j(2)]
//   j=0 -> k2 = q*8+kq, j=1 -> k2 = q*8+kq+4
__device__ uint32_t g_wb[NGROUP*NTAP*16*4*64*2];

__global__ void prep_weights(const float* __restrict__ w1, const float* __restrict__ w2,
                             const float* __restrict__ w3, const float* __restrict__ w4) {
    int idx = blockIdx.x * blockDim.x + threadIdx.x;     // pair index
    if (idx >= NGROUP*NTAP*16*4*64) return;
    int co = idx & 63;
    int kq = (idx >> 6) & 3;
    int q  = (idx >> 8) & 15;
    int gt = idx >> 12;              // g*5 + t
    int t = gt % 5, g = gt / 5;
    const float* w = g==0?w1:g==1?w2:g==2?w3:w4;
    #pragma unroll
    for (int j = 0; j < 2; j++) {
        int k2 = q*8 + kq + j*4;
        int c0 = 2*k2;
        float v0 = w[((size_t)co*C_IN + c0    )*NTAP + t];
        float v1 = w[((size_t)co*C_IN + c0 + 1)*NTAP + t];
        uint32_t lo = (v0 < 0.f) ? 0xBC00u : 0x3C00u;    // fp16 -1 / +1
        uint32_t hi = (v1 < 0.f) ? 0xBC00u : 0x3C00u;
        g_wb[idx*2 + j] = (hi << 16) | lo;
    }
}

__device__ __forceinline__ uint32_t pack_h2(float a, float b) {
    uint32_t r;
    asm("cvt.rn.f16x2.f32 %0, %1, %2;" : "=r"(r) : "f"(b), "f"(a));
    return r;
}

// Transpose-convert: NCHW fp32 -> [img][pix][c2] half2. Block = 32 pix x 256 ch.
__global__ void convert_x(const float* __restrict__ x) {
    __shared__ float sm[32][257];
    const int bx = blockIdx.x;
    const int img = bx >> 9, pix0 = (bx & 511) * 32;
    const int tid = threadIdx.x;
    const float* xi = x + (size_t)img * C_IN * IMG + pix0;
    #pragma unroll
    for (int it = 0; it < 64; it++) {
        int u = it*128 + tid;
        int c = u >> 5, p = u & 31;
        sm[p][c] = xi[(size_t)c * IMG + p];       // coalesced 128B reads
    }
    __syncthreads();
    uint32_t* ob = g_xh + ((size_t)img * IMG + pix0) * 128;
    #pragma unroll
    for (int it = 0; it < 32; it++) {
        int p = it, c2 = tid;                     // 128 threads = 128 c2
        ob[(size_t)p * 128 + c2] = pack_h2(sm[p][2*c2], sm[p][2*c2+1]);
    }
}

#define MMA_F16(cd, A0,A1,A2,A3, B0,B1)                                      \
  asm volatile("mma.sync.aligned.m16n8k16.row.col.f32.f16.f16.f32 "          \
    "{%0,%1,%2,%3},{%4,%5,%6,%7},{%8,%9},{%0,%1,%2,%3};\n"                   \
    : "+f"(cd[0]), "+f"(cd[1]), "+f"(cd[2]), "+f"(cd[3])                     \
    : "r"(A0), "r"(A1), "r"(A2), "r"(A3), "r"(B0), "r"(B1))

#define LDSM4(r0,r1,r2,r3, addr)                                             \
  asm volatile("ldmatrix.sync.aligned.m8n8.x4.shared.b16 {%0,%1,%2,%3}, [%4];" \
    : "=r"(r0), "=r"(r1), "=r"(r2), "=r"(r3) : "r"(addr))

__device__ __forceinline__ void cp_async16(uint32_t dst, const void* src, int src_bytes) {
    asm volatile("cp.async.cg.shared.global [%0], [%1], 16, %2;\n"
                 :: "r"(dst), "l"(src), "r"(src_bytes));
}
__device__ __forceinline__ void cp_commit()  { asm volatile("cp.async.commit_group;\n"); }
__device__ __forceinline__ void cp_wait0()   { asm volatile("cp.async.wait_group 0;\n"); }

// CTA: M=128 pixels x N=64 co. 128 threads = 4 warps (2M x 2N), warp tile 64x32.
// A via ldmatrix.x4 on swizzled pixel-major smem; B via LDS.64 pairs.
// Grid: blockIdx.y = orientation; blockIdx.x = (img,tile)*2 + dil — dilation twins
// are adjacent, co-resident, and share their x A-tiles through L2 (same pixels,
// identical control flow; only shift constants differ).
__global__ __launch_bounds__(128, 4) void mrb_conv_kernel(
    const float* __restrict__ bb1, const float* __restrict__ bb2,
    const float* __restrict__ bb3, const float* __restrict__ bb4,
    float* __restrict__ out)
{
    __shared__ uint32_t SA[2][AS_SZ];      // 2 x 8 KB
    __shared__ uint32_t SB[2][BS_SZ];      // 2 x 10.6 KB

    const int orient = blockIdx.y;        // 0: (1,5) horiz  1: (5,1) vert
    const int dil    = blockIdx.x & 1;    // dilation twin bit (fastest)
    const int g      = orient*2 + dil;    // 0:(1,5)d1 1:(1,5)d2 2:(5,1)d1 3:(5,1)d2
    const bool vert = (orient != 0);
    const bool dil2 = (dil != 0);
    const int tile = blockIdx.x >> 1;     // 128 tiles per image
    const int n = tile >> 7;
    int h0, w0 = 0;
    if (!vert) {
        h0 = tile & 127;                            // 1 row x 128 w
    } else {
        int r = tile & 127;
        h0 = (r >> 3) * 8;  w0 = (r & 7) * 16;      // 8 h x 16 w
    }

    const uint32_t* xb = g_xh + (size_t)n * IMG * 128;   // [pix][c2]

    const int tid  = threadIdx.x;
    const int lane = tid & 31, warp = tid >> 5;
    const int wm = warp >> 1, wn = warp & 1;
    const int qrow = lane >> 2, qcol = lane & 3;

    // ldmatrix lane roles
    const int lrow   = lane & 7;
    const int lm8    = (lane >> 3) & 1;
    const uint32_t khalf16 = (uint32_t)(lane >> 4) << 4;

    float acc[4][4][4];
    #pragma unroll
    for (int i = 0; i < 4; i++)
        #pragma unroll
        for (int j = 0; j < 4; j++)
            #pragma unroll
            for (int r = 0; r < 4; r++) acc[i][j][r] = 0.f;

    // per-mt lane base pixel (row within M tile, before tap shift)
    int pbase[4];
    #pragma unroll
    for (int mt = 0; mt < 4; mt++) {
        int m = wm*64 + mt*16 + lrow + lm8*8;   // 0..127
        pbase[mt] = vert ? (((m >> 4) + 4) * 16 + (m & 15)) : (4 + m);
    }

    const uint32_t saA0 = (uint32_t)__cvta_generic_to_shared(&SA[0][0]);
    const uint32_t saA1 = (uint32_t)__cvta_generic_to_shared(&SA[1][0]);
    const uint32_t sbB0 = (uint32_t)__cvta_generic_to_shared(&SB[0][0]);
    const uint32_t sbB1 = (uint32_t)__cvta_generic_to_shared(&SB[1][0]);

    // issue cp.async copies for chunk q (8 k2 = 16 ch) into stage `buf`
    auto issue = [&](int q, int buf) {
        const uint32_t aB = buf ? saA1 : saA0;
        const uint32_t bB = buf ? sbB1 : sbB0;
        const int k0 = q * 8;             // word offset inside pixel record
        if (!vert) {
            // 136 pixels x 2 chunks = 272 ops
            #pragma unroll
            for (int i = 0; i < 3; i++) {
                int o = tid + i*128;
                if (o < 272) {
                    int pix = o >> 1, h = o & 1;
                    int w = pix - 4;
                    int ok = ((unsigned)w < (unsigned)HW) ? 16 : 0;
                    const uint32_t* src = xb + ((size_t)(h0*HW + (ok ? w : 0)))*128 + k0 + h*4;
                    uint32_t dst = (uint32_t)(pix << 5) + (uint32_t)(h << 4);
                    dst ^= (uint32_t)(pix & 4) << 2;
                    cp_async16(aB + dst, src, ok);
                }
            }
        } else {
            // 256 pixels (16 rows incl halo x 16 w) x 2 chunks = 512 ops
            #pragma unroll
            for (int i = 0; i < 4; i++) {
                int o = tid + i*128;
                int pix = o >> 1, h = o & 1;
                int row = pix >> 4, ww = pix & 15;
                int grow = h0 - 4 + row;
                int ok = ((unsigned)grow < (unsigned)HW) ? 16 : 0;
                const uint32_t* src = xb + ((size_t)((ok ? grow : 0)*HW + w0 + ww))*128 + k0 + h*4;
                uint32_t dst = (uint32_t)(pix << 5) + (uint32_t)(h << 4);
                dst ^= (uint32_t)(pix & 4) << 2;
                cp_async16(aB + dst, src, ok);
            }
        }
        // B paired: 20 rows x 32 x 16B = 640 chunks; 5 per thread
        #pragma unroll
        for (int i = 0; i < 5; i++) {
            int fi = tid + i*128;             // [0,640)
            int c16 = fi & 31, r = fi >> 5;   // r = t*4+kq in [0,20)
            int t = r >> 2, kq = r & 3;
            const uint32_t* srcb =
                g_wb + ((((size_t)(g*NTAP + t)*16 + q)*4 + kq)*64 + c16*2)*2;
            uint32_t dst = bB + (uint32_t)(r*BROW + c16*4) * 4;
            cp_async16(dst, srcb, 16);
        }
        cp_commit();
    };

    issue(0, 0);
    for (int q = 0; q < NCHUNK; q++) {
        cp_wait0();
        __syncthreads();                 // chunk q visible; all warps past chunk q-1 MMAs
        if (q + 1 < NCHUNK) issue(q + 1, (q + 1) & 1);   // overlaps MMAs below

        const uint32_t aStage = (q & 1) ? saA1 : saA0;
        const uint2*   BsP    = reinterpret_cast<const uint2*>(&SB[q & 1][0]);
        #pragma unroll
        for (int t = 0; t < NTAP; t++) {
            int d  = dil2 ? (2*t - 4) : (t - 2);
            int sh = vert ? d * 16 : d;          // tap = pixel shift of A fragment
            uint2 bp[4];
            #pragma unroll
            for (int nt = 0; nt < 4; nt++) {
                int col = wn*32 + nt*8 + qrow;
                bp[nt] = BsP[(t*4 + qcol) * (BROW/2) + col];
            }
            #pragma unroll
            for (int mt = 0; mt < 4; mt++) {
                int p = pbase[mt] + sh;
                uint32_t byte = ((uint32_t)p << 5) + khalf16;
                byte ^= (uint32_t)(p & 4) << 2;
                uint32_t a0, a1, a2, a3;
                LDSM4(a0, a1, a2, a3, aStage + byte);
                #pragma unroll
                for (int nt = 0; nt < 4; nt++)
                    MMA_F16(acc[mt][nt], a0, a1, a2, a3, bp[nt].x, bp[nt].y);
            }
        }
    }

    // Epilogue: bias + store
    const float* bias = (g==0) ? bb1 : (g==1) ? bb2 : (g==2) ? bb3 : bb4;
    float* ob = out + ((size_t)n * 256 + g * 64) * IMG;
    #pragma unroll
    for (int nt = 0; nt < 4; nt++) {
        #pragma unroll
        for (int r = 0; r < 4; r++) {
            int co = wn*32 + nt*8 + 2*qcol + (r & 1);
            float bv = bias[co];
            #pragma unroll
            for (int mt = 0; mt < 4; mt++) {
                int m = wm*64 + mt*16 + qrow + ((r >> 1) << 3);
                int pix = vert ? ((h0 + (m >> 4)) * HW + w0 + (m & 15))
                               : (h0 * HW + m);
                ob[(size_t)co * IMG + pix] = acc[mt][nt][r] + bv;
            }
        }
    }
}

extern "C" void kernel_launch(void* const* d_in, const int* in_sizes, int n_in,
                              void* d_out, int out_size) {
    const float* x  = (const float*)d_in[0];
    const float* w1 = (const float*)d_in[1];
    const float* b1 = (const float*)d_in[2];
    const float* w2 = (const float*)d_in[3];
    const float* b2 = (const float*)d_in[4];
    const float* w3 = (const float*)d_in[5];
    const float* b3 = (const float*)d_in[6];
    const float* w4 = (const float*)d_in[7];
    const float* b4 = (const float*)d_in[8];
    float* out = (float*)d_out;

    prep_weights<<<(NGROUP*NTAP*16*4*64 + 255)/256, 256>>>(w1, w2, w3, w4);
    convert_x<<<16*512, 128>>>(x);
    dim3 grid(16 * 128 * 2, 2);   // (img,tile) x dil fastest; y = orientation
    mrb_conv_kernel<<<grid, 128>>>(b1, b2, b3, b4, out);
}